// round 2
// baseline (speedup 1.0000x reference)
#include <cuda_runtime.h>
#include <math.h>
#include <stdint.h>
#include <stddef.h>

// Problem dims
// B=64, T=80, F=4096, H=512, 3H=1536, Wd=6000, L=32
#define NB   64
#define NT   80
#define NF   4096
#define NH   512
#define NG   1536
#define NWD  6000
#define NL   32
#define BHSZ (NB*NH)          // 32768
#define OUTROW ((size_t)NL*NWD) // 192000 floats per batch row of probs

// ---------------- device scratch (static: no allocations allowed) ----------------
__device__ float g_gi [NT*NB*NG];   // gi_v  (80*64*1536)
__device__ float g_gic[NT*NB*NG];   // gi_c
__device__ float g_enc[NT*NB*NH];   // enc_out
__device__ float g_h1 [2*BHSZ];     // enc_v hidden ping-pong
__device__ float g_h2 [2*BHSZ];     // enc_c hidden ping-pong, then decoder h_v ping-pong
__device__ float g_hcd[BHSZ];       // decoder h_c
__device__ float g_p1 [8*NB*NG];    // split-K partials (gh)
__device__ float g_p2 [8*NB*NG];    // split-K partials (gi, decoder)
__device__ float g_p3 [2*NB*NWD];   // split-K partials (logits)
__device__ float g_lpart[NB];       // per-batch loss partials

// packed fp32x2 FMA (Blackwell; PTX-only, ptxas never auto-fuses)
#define FMA2(d,a,b) asm("fma.rn.f32x2 %0, %1, %2, %0;" : "+l"(d) : "l"(a), "l"(b))

// ---------------- generic tiled GEMM: C[m,n] = sum_k A[m,k]*B[n,k] (+bias) ----------------
// BM=BN=64, BK=16, 128 threads, per-thread 8x4 via f32x2 pairs along m.
// amode==1: A row m maps to x[(m&63)*80 + (m>>6)] (x is (B,T,F), M index is t*B+b)
// split-K: gridDim.z chunks of kc; chunk z writes to C + z*partMN (no bias on partials)
__global__ __launch_bounds__(128) void gemm_k(
    const float* __restrict__ A, const float* __restrict__ B,
    const float* __restrict__ bias, float* __restrict__ C,
    int M, int N, int K, int lda, int ldb, int ldc,
    int amode, int kc, int partMN)
{
    __shared__ __align__(16) float As[16][64];
    __shared__ __align__(16) float Bs[16][72];   // pad 8 -> 288B row stride (16B aligned)
    const int tid = threadIdx.x;
    const int bn0 = blockIdx.x * 64;
    const int bm0 = blockIdx.y * 64;
    const int z   = blockIdx.z;
    const int k0  = z * kc;
    float* Cp = C + (size_t)z * (size_t)partMN;

    const int lrow = tid >> 1;        // 0..63
    const int lk   = (tid & 1) * 8;   // 0 or 8
    const int am   = bm0 + lrow;
    const float* arow;
    if (amode == 1) { int b_ = am & 63, t_ = am >> 6; arow = A + ((size_t)b_ * NT + t_) * (size_t)lda; }
    else            { arow = A + (size_t)am * (size_t)lda; }
    const float* brow = B + (size_t)(bn0 + lrow) * (size_t)ldb;
    const bool bval = (bn0 + lrow) < N;

    const int ty = tid >> 4;   // 0..7  -> m = ty*8
    const int tx = tid & 15;   // 0..15 -> n = tx*4

    unsigned long long acc[4][4];
    #pragma unroll
    for (int i = 0; i < 4; i++)
        #pragma unroll
        for (int j = 0; j < 4; j++) acc[i][j] = 0ull;

    for (int kk = k0; kk < k0 + kc; kk += 16) {
        float4 a0 = *(const float4*)(arow + kk + lk);
        float4 a1 = *(const float4*)(arow + kk + lk + 4);
        float4 b0 = make_float4(0.f,0.f,0.f,0.f), b1 = make_float4(0.f,0.f,0.f,0.f);
        if (bval) { b0 = *(const float4*)(brow + kk + lk); b1 = *(const float4*)(brow + kk + lk + 4); }
        As[lk+0][lrow]=a0.x; As[lk+1][lrow]=a0.y; As[lk+2][lrow]=a0.z; As[lk+3][lrow]=a0.w;
        As[lk+4][lrow]=a1.x; As[lk+5][lrow]=a1.y; As[lk+6][lrow]=a1.z; As[lk+7][lrow]=a1.w;
        Bs[lk+0][lrow]=b0.x; Bs[lk+1][lrow]=b0.y; Bs[lk+2][lrow]=b0.z; Bs[lk+3][lrow]=b0.w;
        Bs[lk+4][lrow]=b1.x; Bs[lk+5][lrow]=b1.y; Bs[lk+6][lrow]=b1.z; Bs[lk+7][lrow]=b1.w;
        __syncthreads();
        #pragma unroll
        for (int k = 0; k < 16; k++) {
            const float* ap = &As[k][ty*8];
            unsigned long long av[4];
            av[0] = *(const unsigned long long*)(ap + 0);
            av[1] = *(const unsigned long long*)(ap + 2);
            av[2] = *(const unsigned long long*)(ap + 4);
            av[3] = *(const unsigned long long*)(ap + 6);
            float4 bv = *(const float4*)&Bs[k][tx*4];
            unsigned long long bd0, bd1, bd2, bd3;
            asm("mov.b64 %0,{%1,%1};" : "=l"(bd0) : "f"(bv.x));
            asm("mov.b64 %0,{%1,%1};" : "=l"(bd1) : "f"(bv.y));
            asm("mov.b64 %0,{%1,%1};" : "=l"(bd2) : "f"(bv.z));
            asm("mov.b64 %0,{%1,%1};" : "=l"(bd3) : "f"(bv.w));
            #pragma unroll
            for (int i = 0; i < 4; i++) {
                FMA2(acc[i][0], av[i], bd0);
                FMA2(acc[i][1], av[i], bd1);
                FMA2(acc[i][2], av[i], bd2);
                FMA2(acc[i][3], av[i], bd3);
            }
        }
        __syncthreads();
    }

    #pragma unroll
    for (int i = 0; i < 4; i++) {
        int m = bm0 + ty*8 + 2*i;
        #pragma unroll
        for (int j = 0; j < 4; j++) {
            int n = bn0 + tx*4 + j;
            if (n < N) {
                float lo, hi;
                asm("mov.b64 {%0,%1}, %2;" : "=f"(lo), "=f"(hi) : "l"(acc[i][j]));
                float bb = bias ? bias[n] : 0.f;
                Cp[(size_t)m * ldc + n]     = lo + bb;
                Cp[(size_t)(m+1) * ldc + n] = hi + bb;
            }
        }
    }
}

// ---------------- GRU gates: h2 = (1-z)*n + z*h, fused partial-sum + bias + embed ----------------
// gim: 0 = gi from precomputed array (incl. bias); 1 = gi = bih only; 2 = gi = sum(parts)+bih+embed
__global__ void gates_k(const float* __restrict__ ghp, int nch,
                        const float* __restrict__ bhh, int gim,
                        const float* __restrict__ gi_src, const float* __restrict__ bih,
                        const float* __restrict__ Wc, const int* __restrict__ yprev,
                        const float* __restrict__ h_in, float* __restrict__ h_out,
                        float* __restrict__ enc_out)
{
    int idx = blockIdx.x * blockDim.x + threadIdx.x;
    if (idx >= NB*NH) return;
    int b = idx >> 9, j = idx & 511;
    float ghr = bhh[j], ghz = bhh[NH + j], ghn = bhh[2*NH + j];
    for (int c = 0; c < nch; c++) {
        const float* p = ghp + (size_t)c * NB * NG + (size_t)b * NG;
        ghr += p[j]; ghz += p[NH + j]; ghn += p[2*NH + j];
    }
    float gir, giz, gin;
    if (gim == 0) {
        const float* g = gi_src + (size_t)b * NG;
        gir = g[j]; giz = g[NH + j]; gin = g[2*NH + j];
    } else {
        gir = bih[j]; giz = bih[NH + j]; gin = bih[2*NH + j];
        if (gim == 2) {
            for (int c = 0; c < nch; c++) {
                const float* p = gi_src + (size_t)c * NB * NG + (size_t)b * NG;
                gir += p[j]; giz += p[NH + j]; gin += p[2*NH + j];
            }
            int w = yprev[b];
            gir += Wc[(size_t)j        * (NH + NWD) + NH + w];
            giz += Wc[(size_t)(NH + j) * (NH + NWD) + NH + w];
            gin += Wc[(size_t)(2*NH+j) * (NH + NWD) + NH + w];
        }
    }
    float r  = 1.f / (1.f + expf(-(gir + ghr)));
    float zz = 1.f / (1.f + expf(-(giz + ghz)));
    float nn = tanhf(gin + r * ghn);
    float h2 = (1.f - zz) * nn + zz * h_in[idx];
    h_out[idx] = h2;
    if (enc_out) enc_out[idx] = h2;
}

// ---------------- misc ----------------
__global__ void init_probs_k(float* __restrict__ out) {
    int idx = blockIdx.x * blockDim.x + threadIdx.x;
    if (idx < NB * NWD) {
        int b = idx / NWD, n = idx % NWD;
        out[(size_t)b * OUTROW + n] = (b == 0 && n == 1) ? 1.f : 0.f;
    }
}
__global__ void zero2_k(float* __restrict__ a, float* __restrict__ b) {
    int idx = blockIdx.x * blockDim.x + threadIdx.x;
    if (idx < BHSZ) { a[idx] = 0.f; b[idx] = 0.f; }
}
// sum 2 logits partials + bias -> probs[:, l, :]
__global__ void logits_asm_k(const float* __restrict__ part, const float* __restrict__ bout,
                             float* __restrict__ outl) {
    int idx = blockIdx.x * blockDim.x + threadIdx.x;
    if (idx < NB * NWD) {
        int b = idx / NWD, n = idx % NWD;
        float v = part[(size_t)b * NWD + n] + part[(size_t)NB * NWD + (size_t)b * NWD + n] + bout[n];
        outl[(size_t)b * OUTROW + n] = v;
    }
}
__global__ void loss1_k(const float* __restrict__ out, const int* __restrict__ y,
                        float* __restrict__ part) {
    int b = blockIdx.x;
    const float* row = out + (size_t)b * OUTROW + (size_t)(NL - 1) * NWD;
    __shared__ float red[256];
    float m = -1e30f;
    for (int i = threadIdx.x; i < NWD; i += 256) m = fmaxf(m, row[i]);
    red[threadIdx.x] = m; __syncthreads();
    for (int s = 128; s > 0; s >>= 1) { if (threadIdx.x < s) red[threadIdx.x] = fmaxf(red[threadIdx.x], red[threadIdx.x + s]); __syncthreads(); }
    m = red[0]; __syncthreads();
    float sum = 0.f;
    for (int i = threadIdx.x; i < NWD; i += 256) sum += expf(row[i] - m);
    red[threadIdx.x] = sum; __syncthreads();
    for (int s = 128; s > 0; s >>= 1) { if (threadIdx.x < s) red[threadIdx.x] += red[threadIdx.x + s]; __syncthreads(); }
    if (threadIdx.x == 0) {
        int t = y[(NL - 1) * NB + b];
        part[b] = -(row[t] - m - logf(red[0]));
    }
}
__global__ void loss2_k(const float* __restrict__ part, float* __restrict__ out) {
    if (threadIdx.x == 0) {
        float s = 0.f;
        for (int b = 0; b < NB; b++) s += part[b];
        out[(size_t)NB * NL * NWD] = s / (float)NB;
    }
}

// ---------------- launch ----------------
extern "C" void kernel_launch(void* const* d_in, const int* in_sizes, int n_in,
                              void* d_out, int out_size) {
    const float* x     = (const float*)d_in[0];
    const int*   y     = (const int*)  d_in[1];
    const float* Wih_v = (const float*)d_in[2];
    const float* Whh_v = (const float*)d_in[3];
    const float* bih_v = (const float*)d_in[4];
    const float* bhh_v = (const float*)d_in[5];
    const float* Wih_c = (const float*)d_in[6];
    const float* Whh_c = (const float*)d_in[7];
    const float* bih_c = (const float*)d_in[8];
    const float* bhh_c = (const float*)d_in[9];
    const float* Wout  = (const float*)d_in[10];
    const float* bout  = (const float*)d_in[11];
    float* out = (float*)d_out;

    float *gi, *gic, *enc, *h1, *h2, *hcd, *p1, *p2, *p3, *lp;
    cudaGetSymbolAddress((void**)&gi,  g_gi);
    cudaGetSymbolAddress((void**)&gic, g_gic);
    cudaGetSymbolAddress((void**)&enc, g_enc);
    cudaGetSymbolAddress((void**)&h1,  g_h1);
    cudaGetSymbolAddress((void**)&h2,  g_h2);
    cudaGetSymbolAddress((void**)&hcd, g_hcd);
    cudaGetSymbolAddress((void**)&p1,  g_p1);
    cudaGetSymbolAddress((void**)&p2,  g_p2);
    cudaGetSymbolAddress((void**)&p3,  g_p3);
    cudaGetSymbolAddress((void**)&lp,  g_lpart);

    init_probs_k<<<(NB*NWD + 255)/256, 256>>>(out);
    zero2_k<<<(BHSZ + 255)/256, 256>>>(h1, h2);

    // gi_v = x @ Wih_v^T + bih_v   (5120 x 1536 x 4096), x row-mapped
    gemm_k<<<dim3(NG/64, (NT*NB)/64, 1), 128>>>(x, Wih_v, bih_v, gi,
        NT*NB, NG, NF, NF, NF, NG, 1, NF, 0);

    // encoder-v scan
    for (int t = 0; t < NT; t++) {
        const float* hin = h1 + (t & 1) * BHSZ;
        float* hout      = h1 + ((t + 1) & 1) * BHSZ;
        gemm_k<<<dim3(NG/64, 1, 8), 128>>>(hin, Whh_v, nullptr, p1,
            NB, NG, NH, NH, NH, NG, 0, 64, NB*NG);
        gates_k<<<(NB*NH)/256, 256>>>(p1, 8, bhh_v, 0, gi + (size_t)t*NB*NG,
            nullptr, nullptr, nullptr, hin, hout, enc + (size_t)t*NB*NH);
    }

    // gi_c = enc_out @ Wih_c[:, :H]^T + bih_c
    gemm_k<<<dim3(NG/64, (NT*NB)/64, 1), 128>>>(enc, Wih_c, bih_c, gic,
        NT*NB, NG, NH, NH, NH + NWD, NG, 0, NH, 0);

    // encoder-c scan
    for (int t = 0; t < NT; t++) {
        const float* hin = h2 + (t & 1) * BHSZ;
        float* hout      = h2 + ((t + 1) & 1) * BHSZ;
        gemm_k<<<dim3(NG/64, 1, 8), 128>>>(hin, Whh_c, nullptr, p1,
            NB, NG, NH, NH, NH, NG, 0, 64, NB*NG);
        gates_k<<<(NB*NH)/256, 256>>>(p1, 8, bhh_c, 0, gic + (size_t)t*NB*NG,
            nullptr, nullptr, nullptr, hin, hout, nullptr);
    }
    // hidden_video now in h2[0]

    // decoder: 31 steps
    for (int s = 0; s < NL - 1; s++) {
        const float* hv_in = h2 + (s & 1) * BHSZ;
        float* hv2         = h2 + ((s + 1) & 1) * BHSZ;
        // h_v2 = gru(gi=bih_v, h_v; Whh_v, bhh_v)
        gemm_k<<<dim3(NG/64, 1, 8), 128>>>(hv_in, Whh_v, nullptr, p1,
            NB, NG, NH, NH, NH, NG, 0, 64, NB*NG);
        gates_k<<<(NB*NH)/256, 256>>>(p1, 8, bhh_v, 1, nullptr, bih_v,
            nullptr, nullptr, hv_in, hv2, nullptr);
        // gi = h_v2 @ Wih_c[:, :H]^T (+ embed + bih_c later)
        gemm_k<<<dim3(NG/64, 1, 8), 128>>>(hv2, Wih_c, nullptr, p2,
            NB, NG, NH, NH, NH + NWD, NG, 0, 64, NB*NG);
        // gh = h_v2 @ Whh_c^T
        gemm_k<<<dim3(NG/64, 1, 8), 128>>>(hv2, Whh_c, nullptr, p1,
            NB, NG, NH, NH, NH, NG, 0, 64, NB*NG);
        // h_c = gru(gi, h_v2; Whh_c, bhh_c)  with gi = sum(p2)+bih_c+Wih_c[:,H+y]
        gates_k<<<(NB*NH)/256, 256>>>(p1, 8, bhh_c, 2, p2, bih_c,
            Wih_c, y + s * NB, hv2, hcd, nullptr);
        // logits = h_c @ Wout^T + bout  -> probs[:, s+1, :]
        gemm_k<<<dim3((NWD + 63)/64, 1, 2), 128>>>(hcd, Wout, nullptr, p3,
            NB, NWD, NH, NH, NH, NWD, 0, 256, NB*NWD);
        logits_asm_k<<<(NB*NWD + 255)/256, 256>>>(p3, bout, out + (size_t)(s + 1) * NWD);
    }

    loss1_k<<<NB, 256>>>(out, y, lp);
    loss2_k<<<1, 32>>>(lp, out);
}

// round 3
// speedup vs baseline: 1.2693x; 1.2693x over previous
#include <cuda_runtime.h>
#include <math.h>
#include <stdint.h>
#include <stddef.h>

#define NB 64
#define NT 80
#define NF 4096
#define NH 512
#define NG 1536
#define NWD 6000
#define NL 32
#define BHSZ (NB*NH)
#define OUTROW ((size_t)NL*NWD)

#define HP 516
#define WP 66
#define PBS (12*64)
#define SMEM_FLOATS (64*HP + 8*12*WP + 8*PBS)
#define SMEM_BYTES (SMEM_FLOATS*4)

__device__ float g_gi [NT*NB*NG];
__device__ float g_gic[NT*NB*NG];
__device__ float g_enc[NT*NB*NH];
__device__ float g_h1 [2*BHSZ];
__device__ float g_h2 [2*BHSZ];
__device__ float g_hcd[BHSZ];
__device__ float g_lpart[NB];
__device__ unsigned g_barrier;

#define FMA2(d,a,b) asm("fma.rn.f32x2 %0, %1, %2, %0;" : "+l"(d) : "l"(a), "l"(b))
__device__ __forceinline__ float sigm(float x){ return 1.f/(1.f+expf(-x)); }

__device__ __forceinline__ void gridbar(unsigned& gen){
    __syncthreads();
    if (threadIdx.x == 0){
        gen += gridDim.x;
        __threadfence();
        atomicAdd(&g_barrier, 1u);
        while (*(volatile unsigned*)&g_barrier < gen) __nanosleep(32);
        __threadfence();
    }
    __syncthreads();
}

__device__ __forceinline__ void stage_h(const float* __restrict__ src, float* __restrict__ hs){
    int t = threadIdx.x;
    #pragma unroll
    for (int i = 0; i < 32; i++){
        int lin = (i*256 + t)*4;
        int b = lin >> 9, k = lin & 511;
        *(float4*)(hs + b*HP + k) = *(const float4*)(src + lin);
    }
}

// stage 12 weight rows (this warp's 64-wide k chunk)
// gmode=1: row r -> (r>>2)*NH + base + (r&3); gmode=0: row r -> base + r
__device__ __forceinline__ void stage_w(const float* __restrict__ W, int ld, int base,
                                        int gmode, int kbase, float* __restrict__ dst){
    int lane = threadIdx.x & 31;
    #pragma unroll
    for (int r = 0; r < 12; r++){
        int row = gmode ? ((r>>2)*NH + base + (r&3)) : (base + r);
        float2 v = *(const float2*)(W + (size_t)row*ld + kbase + 2*lane);
        *(float2*)(dst + r*WP + 2*lane) = v;
    }
    __syncwarp();
}

// 64 rows x 12 cols over this warp's 64-wide k chunk
__device__ __forceinline__ void micro_mm(const float* __restrict__ hs,
                                         const float* __restrict__ wr,
                                         float* __restrict__ pb, int kbase){
    int lane = threadIdx.x & 31;
    int cjp = lane & 3, mg = lane >> 2;
    unsigned long long acc[8][3];
    #pragma unroll
    for (int i = 0; i < 8; i++){ acc[i][0]=0ull; acc[i][1]=0ull; acc[i][2]=0ull; }
    const float* hp = hs + mg*HP + kbase;
    const float* w0 = wr + cjp*WP;
    #pragma unroll 4
    for (int k = 0; k < 64; k += 2){
        unsigned long long wv0 = *(const unsigned long long*)(w0 + k);
        unsigned long long wv1 = *(const unsigned long long*)(w0 + 4*WP + k);
        unsigned long long wv2 = *(const unsigned long long*)(w0 + 8*WP + k);
        #pragma unroll
        for (int i = 0; i < 8; i++){
            unsigned long long a = *(const unsigned long long*)(hp + i*8*HP + k);
            FMA2(acc[i][0], a, wv0);
            FMA2(acc[i][1], a, wv1);
            FMA2(acc[i][2], a, wv2);
        }
    }
    #pragma unroll
    for (int i = 0; i < 8; i++){
        int m = mg + 8*i;
        #pragma unroll
        for (int g = 0; g < 3; g++){
            float lo, hi;
            asm("mov.b64 {%0,%1}, %2;" : "=f"(lo), "=f"(hi) : "l"(acc[i][g]));
            pb[(g*4 + cjp)*64 + m] = lo + hi;
        }
    }
}

__device__ __forceinline__ float psum(const float* __restrict__ pbuf, int r, int b){
    float s = 0.f;
    #pragma unroll
    for (int w = 0; w < 8; w++) s += pbuf[(w*12 + r)*64 + b];
    return s;
}

// ---------------- persistent encoder scan ----------------
__global__ __launch_bounds__(256,1) void enc_scan_k(
    const float* __restrict__ Whh, const float* __restrict__ bhh,
    const float* __restrict__ gi_all, float* __restrict__ hbuf,
    float* __restrict__ enc_out)
{
    extern __shared__ float sm[];
    float* hs = sm;
    float* wst = sm + 64*HP;
    float* pbuf = wst + 8*12*WP;
    const int tid = threadIdx.x, w = tid >> 5;
    const int c0 = blockIdx.x*4, kbase = w*64;
    float* wstw = wst + w*12*WP;
    float* pbw = pbuf + w*PBS;
    const int b = tid & 63, cj = tid >> 6;
    unsigned gen = 0;

    stage_w(Whh, NH, c0, 1, kbase, wstw);

    for (int step = 0; step < NT; step++){
        const float* hin = hbuf + (step & 1)*BHSZ;
        float* hout = hbuf + ((step+1) & 1)*BHSZ;
        stage_h(hin, hs);
        __syncthreads();
        micro_mm(hs, wstw, pbw, kbase);
        __syncthreads();
        {
            int c = c0 + cj;
            float ghr = bhh[c]        + psum(pbuf, cj, b);
            float ghz = bhh[NH+c]     + psum(pbuf, 4+cj, b);
            float ghn = bhh[2*NH+c]   + psum(pbuf, 8+cj, b);
            const float* gi = gi_all + ((size_t)step*NB + b)*NG;
            float r  = sigm(gi[c] + ghr);
            float z  = sigm(gi[NH+c] + ghz);
            float nn = tanhf(gi[2*NH+c] + r*ghn);
            float h2 = (1.f - z)*nn + z*hs[b*HP + c];
            hout[b*NH + c] = h2;
            if (enc_out) enc_out[((size_t)step*NB + b)*NH + c] = h2;
        }
        gridbar(gen);
    }
}

// ---------------- persistent decoder ----------------
__global__ __launch_bounds__(256,1) void dec_scan_k(
    const float* __restrict__ Whh_v, const float* __restrict__ bih_v, const float* __restrict__ bhh_v,
    const float* __restrict__ Wih_c, const float* __restrict__ Whh_c,
    const float* __restrict__ bih_c, const float* __restrict__ bhh_c,
    const float* __restrict__ Wout, const float* __restrict__ bout,
    const int* __restrict__ y,
    float* __restrict__ hv, float* __restrict__ hc, float* __restrict__ out)
{
    extern __shared__ float sm[];
    float* hs = sm;
    float* wst = sm + 64*HP;
    float* pbuf = wst + 8*12*WP;
    const int tid = threadIdx.x, w = tid >> 5;
    const int c0 = blockIdx.x*4, kbase = w*64;
    float* wstw = wst + w*12*WP;
    float* pbw = pbuf + w*PBS;
    const int b = tid & 63, cj = tid >> 6;
    unsigned gen = 0;

    for (int s = 0; s < NL-1; s++){
        const float* hv_in = hv + (s & 1)*BHSZ;
        float* hv2 = hv + ((s+1) & 1)*BHSZ;

        // A: h_v2 = GRU(gi=bih_v, h_v)
        stage_h(hv_in, hs);
        stage_w(Whh_v, NH, c0, 1, kbase, wstw);
        __syncthreads();
        micro_mm(hs, wstw, pbw, kbase);
        __syncthreads();
        {
            int c = c0 + cj;
            float ghr = bhh_v[c]      + psum(pbuf, cj, b);
            float ghz = bhh_v[NH+c]   + psum(pbuf, 4+cj, b);
            float ghn = bhh_v[2*NH+c] + psum(pbuf, 8+cj, b);
            float r  = sigm(bih_v[c] + ghr);
            float z  = sigm(bih_v[NH+c] + ghz);
            float nn = tanhf(bih_v[2*NH+c] + r*ghn);
            hv2[b*NH + c] = (1.f - z)*nn + z*hs[b*HP + c];
        }
        gridbar(gen);

        // B: gi = h_v2@Wih_c_h^T ; gh = h_v2@Whh_c^T ; gates -> h_c
        stage_h(hv2, hs);
        stage_w(Wih_c, NH+NWD, c0, 1, kbase, wstw);
        __syncthreads();
        micro_mm(hs, wstw, pbw, kbase);
        __syncthreads();
        float gi0 = psum(pbuf, cj, b);
        float gi1 = psum(pbuf, 4+cj, b);
        float gi2 = psum(pbuf, 8+cj, b);
        __syncthreads();
        stage_w(Whh_c, NH, c0, 1, kbase, wstw);
        micro_mm(hs, wstw, pbw, kbase);
        __syncthreads();
        {
            int c = c0 + cj;
            int yb = y[s*NB + b];
            float ghr = bhh_c[c]      + psum(pbuf, cj, b);
            float ghz = bhh_c[NH+c]   + psum(pbuf, 4+cj, b);
            float ghn = bhh_c[2*NH+c] + psum(pbuf, 8+cj, b);
            float gir = gi0 + bih_c[c]      + Wih_c[(size_t)c*(NH+NWD)        + NH + yb];
            float giz = gi1 + bih_c[NH+c]   + Wih_c[(size_t)(NH+c)*(NH+NWD)   + NH + yb];
            float gin = gi2 + bih_c[2*NH+c] + Wih_c[(size_t)(2*NH+c)*(NH+NWD) + NH + yb];
            float r  = sigm(gir + ghr);
            float z  = sigm(giz + ghz);
            float nn = tanhf(gin + r*ghn);
            hc[b*NH + c] = (1.f - z)*nn + z*hs[b*HP + c];
        }
        gridbar(gen);

        // C: logits = h_c @ Wout^T + bout -> probs[:, s+1, :]
        stage_h(hc, hs);
        __syncthreads();
        for (int pass = 0; pass < 4; pass++){
            int tile = blockIdx.x + 128*pass;
            if (tile < 500){
                stage_w(Wout, NH, tile*12, 0, kbase, wstw);
                micro_mm(hs, wstw, pbw, kbase);
            }
            __syncthreads();
            if (tile < 500){
                #pragma unroll
                for (int g = 0; g < 3; g++){
                    int col = tile*12 + g*4 + cj;
                    float v = psum(pbuf, g*4+cj, b) + bout[col];
                    out[(size_t)b*OUTROW + (size_t)(s+1)*NWD + col] = v;
                }
            }
            __syncthreads();
        }
    }
}

// ---------------- big GEMM (gi_v, gi_c) ----------------
__global__ __launch_bounds__(128) void gemm_k(
    const float* __restrict__ A, const float* __restrict__ B,
    const float* __restrict__ bias, float* __restrict__ C,
    int N, int K, int lda, int ldb, int ldc, int amode)
{
    __shared__ __align__(16) float As[16][64];
    __shared__ __align__(16) float Bs[16][72];
    const int tid = threadIdx.x;
    const int bn0 = blockIdx.x*64;
    const int bm0 = blockIdx.y*64;
    const int lrow = tid >> 1, lk = (tid & 1)*8;
    const int am = bm0 + lrow;
    const float* arow;
    if (amode == 1){ int b_ = am & 63, t_ = am >> 6; arow = A + ((size_t)b_*NT + t_)*(size_t)lda; }
    else arow = A + (size_t)am*(size_t)lda;
    const float* brow = B + (size_t)(bn0 + lrow)*(size_t)ldb;
    const int ty = tid >> 4, tx = tid & 15;

    unsigned long long acc[4][4];
    #pragma unroll
    for (int i = 0; i < 4; i++)
        #pragma unroll
        for (int j = 0; j < 4; j++) acc[i][j] = 0ull;

    for (int kk = 0; kk < K; kk += 16){
        float4 a0 = *(const float4*)(arow + kk + lk);
        float4 a1 = *(const float4*)(arow + kk + lk + 4);
        float4 b0 = *(const float4*)(brow + kk + lk);
        float4 b1 = *(const float4*)(brow + kk + lk + 4);
        As[lk+0][lrow]=a0.x; As[lk+1][lrow]=a0.y; As[lk+2][lrow]=a0.z; As[lk+3][lrow]=a0.w;
        As[lk+4][lrow]=a1.x; As[lk+5][lrow]=a1.y; As[lk+6][lrow]=a1.z; As[lk+7][lrow]=a1.w;
        Bs[lk+0][lrow]=b0.x; Bs[lk+1][lrow]=b0.y; Bs[lk+2][lrow]=b0.z; Bs[lk+3][lrow]=b0.w;
        Bs[lk+4][lrow]=b1.x; Bs[lk+5][lrow]=b1.y; Bs[lk+6][lrow]=b1.z; Bs[lk+7][lrow]=b1.w;
        __syncthreads();
        #pragma unroll
        for (int k = 0; k < 16; k++){
            const float* ap = &As[k][ty*8];
            unsigned long long av[4];
            av[0] = *(const unsigned long long*)(ap+0);
            av[1] = *(const unsigned long long*)(ap+2);
            av[2] = *(const unsigned long long*)(ap+4);
            av[3] = *(const unsigned long long*)(ap+6);
            float4 bv = *(const float4*)&Bs[k][tx*4];
            unsigned long long bd0,bd1,bd2,bd3;
            asm("mov.b64 %0,{%1,%1};" : "=l"(bd0) : "f"(bv.x));
            asm("mov.b64 %0,{%1,%1};" : "=l"(bd1) : "f"(bv.y));
            asm("mov.b64 %0,{%1,%1};" : "=l"(bd2) : "f"(bv.z));
            asm("mov.b64 %0,{%1,%1};" : "=l"(bd3) : "f"(bv.w));
            #pragma unroll
            for (int i = 0; i < 4; i++){
                FMA2(acc[i][0], av[i], bd0);
                FMA2(acc[i][1], av[i], bd1);
                FMA2(acc[i][2], av[i], bd2);
                FMA2(acc[i][3], av[i], bd3);
            }
        }
        __syncthreads();
    }
    #pragma unroll
    for (int i = 0; i < 4; i++){
        int m = bm0 + ty*8 + 2*i;
        #pragma unroll
        for (int j = 0; j < 4; j++){
            int n = bn0 + tx*4 + j;
            float lo, hi;
            asm("mov.b64 {%0,%1}, %2;" : "=f"(lo), "=f"(hi) : "l"(acc[i][j]));
            float bb = bias[n];
            C[(size_t)m*ldc + n]     = lo + bb;
            C[(size_t)(m+1)*ldc + n] = hi + bb;
        }
    }
}

// ---------------- misc ----------------
__global__ void init_k(float* __restrict__ out, float* __restrict__ h1, float* __restrict__ h2){
    int idx = blockIdx.x*blockDim.x + threadIdx.x;
    if (idx < NB*NWD){
        int b = idx / NWD, n = idx % NWD;
        out[(size_t)b*OUTROW + n] = (b == 0 && n == 1) ? 1.f : 0.f;
    }
    if (idx < BHSZ){ h1[idx] = 0.f; h2[idx] = 0.f; }
    if (idx == 0) g_barrier = 0u;
}
__global__ void bar0_k(){ if (threadIdx.x == 0) g_barrier = 0u; }
__global__ void loss1_k(const float* __restrict__ out, const int* __restrict__ y,
                        float* __restrict__ part){
    int b = blockIdx.x;
    const float* row = out + (size_t)b*OUTROW + (size_t)(NL-1)*NWD;
    __shared__ float red[256];
    float m = -1e30f;
    for (int i = threadIdx.x; i < NWD; i += 256) m = fmaxf(m, row[i]);
    red[threadIdx.x] = m; __syncthreads();
    for (int s = 128; s > 0; s >>= 1){ if (threadIdx.x < s) red[threadIdx.x] = fmaxf(red[threadIdx.x], red[threadIdx.x+s]); __syncthreads(); }
    m = red[0]; __syncthreads();
    float sum = 0.f;
    for (int i = threadIdx.x; i < NWD; i += 256) sum += expf(row[i] - m);
    red[threadIdx.x] = sum; __syncthreads();
    for (int s = 128; s > 0; s >>= 1){ if (threadIdx.x < s) red[threadIdx.x] += red[threadIdx.x+s]; __syncthreads(); }
    if (threadIdx.x == 0){
        int t = y[(NL-1)*NB + b];
        part[b] = -(row[t] - m - logf(red[0]));
    }
}
__global__ void loss2_k(const float* __restrict__ part, float* __restrict__ out){
    if (threadIdx.x == 0){
        float s = 0.f;
        for (int b = 0; b < NB; b++) s += part[b];
        out[(size_t)NB*NL*NWD] = s/(float)NB;
    }
}

extern "C" void kernel_launch(void* const* d_in, const int* in_sizes, int n_in,
                              void* d_out, int out_size){
    const float* x     = (const float*)d_in[0];
    const int*   y     = (const int*)  d_in[1];
    const float* Wih_v = (const float*)d_in[2];
    const float* Whh_v = (const float*)d_in[3];
    const float* bih_v = (const float*)d_in[4];
    const float* bhh_v = (const float*)d_in[5];
    const float* Wih_c = (const float*)d_in[6];
    const float* Whh_c = (const float*)d_in[7];
    const float* bih_c = (const float*)d_in[8];
    const float* bhh_c = (const float*)d_in[9];
    const float* Wout  = (const float*)d_in[10];
    const float* bout  = (const float*)d_in[11];
    float* out = (float*)d_out;

    float *gi, *gic, *enc, *h1, *h2, *hcd, *lp;
    cudaGetSymbolAddress((void**)&gi,  g_gi);
    cudaGetSymbolAddress((void**)&gic, g_gic);
    cudaGetSymbolAddress((void**)&enc, g_enc);
    cudaGetSymbolAddress((void**)&h1,  g_h1);
    cudaGetSymbolAddress((void**)&h2,  g_h2);
    cudaGetSymbolAddress((void**)&hcd, g_hcd);
    cudaGetSymbolAddress((void**)&lp,  g_lpart);

    cudaFuncSetAttribute(enc_scan_k, cudaFuncAttributeMaxDynamicSharedMemorySize, SMEM_BYTES);
    cudaFuncSetAttribute(dec_scan_k, cudaFuncAttributeMaxDynamicSharedMemorySize, SMEM_BYTES);

    init_k<<<(NB*NWD + 255)/256, 256>>>(out, h1, h2);

    // gi_v = x @ Wih_v^T + bih_v
    gemm_k<<<dim3(NG/64, (NT*NB)/64), 128>>>(x, Wih_v, bih_v, gi, NG, NF, NF, NF, NG, 1);

    enc_scan_k<<<128, 256, SMEM_BYTES>>>(Whh_v, bhh_v, gi, h1, enc);

    // gi_c = enc_out @ Wih_c[:, :H]^T + bih_c
    gemm_k<<<dim3(NG/64, (NT*NB)/64), 128>>>(enc, Wih_c, bih_c, gic, NG, NH, NH, NH+NWD, NG, 0);

    bar0_k<<<1, 32>>>();
    enc_scan_k<<<128, 256, SMEM_BYTES>>>(Whh_c, bhh_c, gic, h2, nullptr);

    bar0_k<<<1, 32>>>();
    dec_scan_k<<<128, 256, SMEM_BYTES>>>(Whh_v, bih_v, bhh_v, Wih_c, Whh_c, bih_c, bhh_c,
                                         Wout, bout, y, h2, hcd, out);

    loss1_k<<<NB, 256>>>(out, y, lp);
    loss2_k<<<1, 32>>>(lp, out);
}